// round 5
// baseline (speedup 1.0000x reference)
#include <cuda_runtime.h>
#include <cuda_bf16.h>
#include <math.h>

// Problem constants
#define BB 8
#define NN 2048
#define MM 2048
#define HH 512
#define KD 64

// ---------------- scratch (no allocations allowed) ----------------
__device__ float g_qn[BB * NN];
__device__ float g_kn[BB * MM];
__device__ float g_w[BB * NN];
__device__ __nv_bfloat16 g_qh[BB * NN * KD];
__device__ __nv_bfloat16 g_ql[BB * NN * KD];
__device__ __nv_bfloat16 g_kh[BB * MM * KD];  // (-2k) hi
__device__ __nv_bfloat16 g_kl[BB * MM * KD];  // (-2k) lo
__device__ __nv_bfloat16 g_wh[2][KD * HH];
__device__ __nv_bfloat16 g_wl[2][KD * HH];

__device__ __forceinline__ unsigned smem_u32(const void* p) {
    unsigned a;
    asm("{ .reg .u64 t; cvta.to.shared.u64 t, %1; cvt.u32.u64 %0, t; }" : "=r"(a) : "l"(p));
    return a;
}

#define CP16(dst, src) asm volatile("cp.async.cg.shared.global [%0], [%1], 16;" :: "r"(dst), "l"(src) : "memory")
#define CP_COMMIT()    asm volatile("cp.async.commit_group;" ::: "memory")
#define CP_WAIT1()     asm volatile("cp.async.wait_group 1;" ::: "memory")
#define CP_WAIT0()     asm volatile("cp.async.wait_group 0;" ::: "memory")

#define LDSM4(r0, r1, r2, r3, a) \
    asm volatile("ldmatrix.sync.aligned.m8n8.x4.shared.b16 {%0,%1,%2,%3}, [%4];" \
                 : "=r"(r0), "=r"(r1), "=r"(r2), "=r"(r3) : "r"(a))

#define MMA16816(c, a, b) \
    asm volatile("mma.sync.aligned.m16n8k16.row.col.f32.bf16.bf16.f32 " \
                 "{%0,%1,%2,%3}, {%4,%5,%6,%7}, {%8,%9}, {%0,%1,%2,%3};" \
                 : "+f"((c)[0]), "+f"((c)[1]), "+f"((c)[2]), "+f"((c)[3]) \
                 : "r"((a)[0]), "r"((a)[1]), "r"((a)[2]), "r"((a)[3]), \
                   "r"((b)[0]), "r"((b)[1]))

__device__ __forceinline__ unsigned pack_bf2(float a, float b) {
    __nv_bfloat162 t = __floats2bfloat162_rn(a, b);
    return *reinterpret_cast<unsigned*>(&t);
}
__device__ __forceinline__ unsigned pack_h2(__nv_bfloat16 a, __nv_bfloat16 b) {
    __nv_bfloat162 t = __halves2bfloat162(a, b);
    return *reinterpret_cast<unsigned*>(&t);
}

// =====================================================================
// Kernel 0: split W into hi/lo bf16
// =====================================================================
__global__ void wsplit_kernel(const float* __restrict__ Wq, const float* __restrict__ Wk)
{
    int i = blockIdx.x * 256 + threadIdx.x;
    int side = i >> 15, j = i & 32767;
    float v = (side ? Wk : Wq)[j];
    __nv_bfloat16 h = __float2bfloat16_rn(v);
    g_wh[side][j] = h;
    g_wl[side][j] = __float2bfloat16_rn(v - __bfloat162float(h));
}

// =====================================================================
// Kernel 1 (v3): HMMA split-bf16 projection, 64-row tiles, 3 CTAs/SM.
// grid = (256, 2), block = 256 (8 warps: 4 M x 2 N).
// smem: xh[8K] xl[8K] | W double buf 2x(Wh 8K + Wl 8K) = 48K.
// =====================================================================
#define PJ_XL   8192
#define PJ_W    16384
#define PJ_SMEM 49152

__global__ __launch_bounds__(256, 3) void proj_kernel(
    const float* __restrict__ X0, const float* __restrict__ Y0,
    const float* __restrict__ bq, const float* __restrict__ bk)
{
    extern __shared__ char smem[];
    const unsigned sb = smem_u32(smem);

    const int side = blockIdx.y;
    const float* X    = side ? Y0 : X0;
    const float* bias = side ? bk : bq;
    const char* gwh = (const char*)g_wh[side];
    const char* gwl = (const char*)g_wl[side];
    float* gnorm = side ? g_kn : g_qn;
    __nv_bfloat16* gh = side ? g_kh : g_qh;
    __nv_bfloat16* gl = side ? g_kl : g_ql;
    const float scale = side ? -2.f : 1.f;

    const int r0 = blockIdx.x * 64;
    const int t  = threadIdx.x;
    const int wid = t >> 5, l = t & 31;
    const int wr = (wid & 3) * 16;     // warp row base (4 x 16 = 64 rows)
    const int wc = (wid >> 2) * 32;    // warp col base (2 x 32 = 64 cols)

    // ---- prologue: x chunk 0 -> regs; W chunk 0 -> smem buf 0 ----
    float4 xbuf[2][2];
#pragma unroll
    for (int it = 0; it < 2; ++it) {
        int c16 = t + 256 * it;            // 0..511 over [64 rows][8 ch]
        int row = c16 >> 3, ch = c16 & 7;
        const float* src = X + (size_t)(r0 + row) * HH + ch * 8;
        xbuf[it][0] = *(const float4*)src;
        xbuf[it][1] = *(const float4*)(src + 4);
    }
#pragma unroll
    for (int it = 0; it < 4; ++it) {
        int f = t + 256 * it;              // 0..1023
        int split = f >> 9, c = f & 511;
        int row = c >> 3, ch = c & 7;
        unsigned dst = sb + PJ_W + split * 8192 + row * 128 + ((ch * 16) ^ ((row & 7) << 4));
        CP16(dst, (split ? gwl : gwh) + row * 1024 + ch * 16);
    }
    CP_COMMIT();

    // ldmatrix geometry
    const int rowA0 = wr + (l & 7) + ((l & 8) ? 8 : 0);
    const int rowB0 = wc + (l & 7) + ((l & 16) ? 8 : 0);
    const int kbA = (l & 16) ? 16 : 0;
    const int kbB = (l & 8) ? 16 : 0;
    const int p = (l & 7) << 4;
    const unsigned aA0 = sb + rowA0 * 128;
    const unsigned aB0 = rowB0 * 128;

    float acc[4][4];
#pragma unroll
    for (int t8 = 0; t8 < 4; ++t8)
#pragma unroll
        for (int e = 0; e < 4; ++e) acc[t8][e] = 0.f;

    for (int i = 0; i < 8; ++i) {
        __syncthreads();
        // convert + store x chunk i
#pragma unroll
        for (int it = 0; it < 2; ++it) {
            int c16 = t + 256 * it;
            int row = c16 >> 3, ch = c16 & 7;
            unsigned off = row * 128 + ((ch * 16) ^ ((row & 7) << 4));
            float4 a = xbuf[it][0], b4 = xbuf[it][1];
            __nv_bfloat16 h0 = __float2bfloat16_rn(a.x), h1 = __float2bfloat16_rn(a.y);
            __nv_bfloat16 h2 = __float2bfloat16_rn(a.z), h3 = __float2bfloat16_rn(a.w);
            __nv_bfloat16 h4 = __float2bfloat16_rn(b4.x), h5 = __float2bfloat16_rn(b4.y);
            __nv_bfloat16 h6 = __float2bfloat16_rn(b4.z), h7 = __float2bfloat16_rn(b4.w);
            uint4 hv = make_uint4(pack_h2(h0, h1), pack_h2(h2, h3),
                                  pack_h2(h4, h5), pack_h2(h6, h7));
            uint4 lv = make_uint4(
                pack_bf2(a.x - __bfloat162float(h0), a.y - __bfloat162float(h1)),
                pack_bf2(a.z - __bfloat162float(h2), a.w - __bfloat162float(h3)),
                pack_bf2(b4.x - __bfloat162float(h4), b4.y - __bfloat162float(h5)),
                pack_bf2(b4.z - __bfloat162float(h6), b4.w - __bfloat162float(h7)));
            *(uint4*)(smem + off) = hv;
            *(uint4*)(smem + PJ_XL + off) = lv;
        }
        if (i < 7) {
#pragma unroll
            for (int it = 0; it < 2; ++it) {
                int c16 = t + 256 * it;
                int row = c16 >> 3, ch = c16 & 7;
                const float* src = X + (size_t)(r0 + row) * HH + (i + 1) * 64 + ch * 8;
                xbuf[it][0] = *(const float4*)src;
                xbuf[it][1] = *(const float4*)(src + 4);
            }
#pragma unroll
            for (int it = 0; it < 4; ++it) {
                int f = t + 256 * it;
                int split = f >> 9, c = f & 511;
                int row = c >> 3, ch = c & 7;
                unsigned dst = sb + PJ_W + ((i + 1) & 1) * 16384 + split * 8192
                               + row * 128 + ((ch * 16) ^ ((row & 7) << 4));
                CP16(dst, (split ? gwl : gwh) + row * 1024 + (i + 1) * 128 + ch * 16);
            }
            CP_COMMIT();
            CP_WAIT1();
        } else {
            CP_WAIT0();
        }
        __syncthreads();

        const unsigned wb = sb + PJ_W + (i & 1) * 16384;
#pragma unroll
        for (int ks = 0; ks < 4; ++ks) {
            const unsigned xbA = (unsigned)((ks * 32 + kbA) ^ p);
            const unsigned xbB = (unsigned)((ks * 32 + kbB) ^ p);
            unsigned ah[4], al[4], bh[4][2], bl[4][2];
            LDSM4(ah[0], ah[1], ah[2], ah[3], aA0 + xbA);
            LDSM4(al[0], al[1], al[2], al[3], aA0 + PJ_XL + xbA);
#pragma unroll
            for (int g = 0; g < 2; ++g) {
                unsigned base = wb + aB0 + g * 2048 + xbB;
                LDSM4(bh[2 * g][0], bh[2 * g][1], bh[2 * g + 1][0], bh[2 * g + 1][1], base);
                LDSM4(bl[2 * g][0], bl[2 * g][1], bl[2 * g + 1][0], bl[2 * g + 1][1], base + 8192);
            }
#pragma unroll
            for (int t8 = 0; t8 < 4; ++t8) {
                MMA16816(acc[t8], ah, bh[t8]);
                MMA16816(acc[t8], ah, bl[t8]);
                MMA16816(acc[t8], al, bh[t8]);
            }
        }
    }

    // ---- epilogue: bias, stage to s_o[64][68], split writeout, norms ----
    __syncthreads();
    float* s_o = (float*)smem;
#pragma unroll
    for (int t8 = 0; t8 < 4; ++t8) {
        int col = wc + t8 * 8 + 2 * (l & 3);
        float2 b2 = *(const float2*)&bias[col];
        int row0 = wr + (l >> 2);
        s_o[row0 * 68 + col]           = acc[t8][0] + b2.x;
        s_o[row0 * 68 + col + 1]       = acc[t8][1] + b2.y;
        s_o[(row0 + 8) * 68 + col]     = acc[t8][2] + b2.x;
        s_o[(row0 + 8) * 68 + col + 1] = acc[t8][3] + b2.y;
    }
    __syncthreads();

#pragma unroll
    for (int it = 0; it < 4; ++it) {
        int f = t + 256 * it;               // 0..1023 over [64 rows][16 quads]
        int quad = f & 15, r = f >> 4;
        float4 v = *(const float4*)&s_o[r * 68 + quad * 4];
        v.x *= scale; v.y *= scale; v.z *= scale; v.w *= scale;
        __nv_bfloat16 h0 = __float2bfloat16_rn(v.x);
        __nv_bfloat16 h1 = __float2bfloat16_rn(v.y);
        __nv_bfloat16 h2 = __float2bfloat16_rn(v.z);
        __nv_bfloat16 h3 = __float2bfloat16_rn(v.w);
        unsigned hp0 = pack_h2(h0, h1), hp1 = pack_h2(h2, h3);
        unsigned lp0 = pack_bf2(v.x - __bfloat162float(h0), v.y - __bfloat162float(h1));
        unsigned lp1 = pack_bf2(v.z - __bfloat162float(h2), v.w - __bfloat162float(h3));
        size_t base = (size_t)(r0 + r) * KD + quad * 4;
        *(unsigned*)&gh[base]     = hp0;
        *(unsigned*)&gh[base + 2] = hp1;
        *(unsigned*)&gl[base]     = lp0;
        *(unsigned*)&gl[base + 2] = lp1;
    }
    if (t < 64) {
        float s = 0.f;
#pragma unroll
        for (int j = 0; j < 64; ++j) {
            float v = s_o[t * 68 + j];
            s += v * v;
        }
        gnorm[r0 + t] = s;
    }
}

// =====================================================================
// Kernel 2: HMMA split-bf16 min-distance kernel.
// A (q) fragments hoisted into registers (1 CTA/SM, regs free).
// =====================================================================
#define OFF_QL   16384
#define OFF_B    32768
#define BUFSZ    33792
#define OFF_QN   (OFF_B + 2 * BUFSZ)
#define OFF_RED  (OFF_QN + 512)
#define DIST_SMEM (OFF_RED + 4096)
#define NT 16

__global__ __launch_bounds__(256) void dist_kernel()
{
    extern __shared__ char smem[];
    const unsigned sb = smem_u32(smem);

    const int b  = blockIdx.y;
    const int n0 = blockIdx.x * 128;
    const int t  = threadIdx.x;
    const int wid = t >> 5, l = t & 31;
    const int wr = (wid & 3) * 32;
    const int wc = (wid >> 2) * 64;

    const char* gqh = (const char*)g_qh + ((size_t)b * NN + n0) * KD * 2;
    const char* gql = (const char*)g_ql + ((size_t)b * NN + n0) * KD * 2;
    const char* gkh = (const char*)g_kh + (size_t)b * MM * KD * 2;
    const char* gkl = (const char*)g_kl + (size_t)b * MM * KD * 2;
    const char* gkn = (const char*)g_kn + (size_t)b * MM * 4;
    const char* gqn = (const char*)g_qn + ((size_t)b * NN + n0) * 4;

    // group 0: A tiles + qn + k tile 0 + kn0
#pragma unroll
    for (int it = 0; it < 8; ++it) {
        int f = t + 256 * it;
        int split = f >> 10, c = f & 1023;
        int row = c >> 3, ch = c & 7;
        unsigned dst = sb + split * 16384 + row * 128 + ((ch * 16) ^ ((row & 7) << 4));
        CP16(dst, (split ? gql : gqh) + c * 16);
    }
    if (t < 32) CP16(sb + OFF_QN + t * 16, gqn + t * 16);
#pragma unroll
    for (int it = 0; it < 8; ++it) {
        int f = t + 256 * it;
        int split = f >> 10, c = f & 1023;
        int row = c >> 3, ch = c & 7;
        unsigned dst = sb + OFF_B + split * 16384 + row * 128 + ((ch * 16) ^ ((row & 7) << 4));
        CP16(dst, (split ? gkl : gkh) + c * 16);
    }
    if (t < 32) CP16(sb + OFF_B + 32768 + t * 16, gkn + t * 16);
    CP_COMMIT();

    // group 1: k tile 1 + kn1
    {
        const char* skh = gkh + (size_t)128 * KD * 2;
        const char* skl = gkl + (size_t)128 * KD * 2;
        unsigned bufb = sb + OFF_B + BUFSZ;
#pragma unroll
        for (int it = 0; it < 8; ++it) {
            int f = t + 256 * it;
            int split = f >> 10, c = f & 1023;
            int row = c >> 3, ch = c & 7;
            unsigned dst = bufb + split * 16384 + row * 128 + ((ch * 16) ^ ((row & 7) << 4));
            CP16(dst, (split ? skl : skh) + c * 16);
        }
        if (t < 32) CP16(bufb + 32768 + t * 16, gkn + 512 + t * 16);
        CP_COMMIT();
    }

    const int rowA0 = wr + (l & 7) + ((l & 8) ? 8 : 0);
    const int rowB0 = wc + (l & 7) + ((l & 16) ? 8 : 0);
    const int kbA = (l & 16) ? 16 : 0;
    const int kbB = (l & 8) ? 16 : 0;
    const int p = (l & 7) << 4;
    const unsigned aA0 = sb + rowA0 * 128;
    const unsigned aB0 = rowB0 * 128;

    CP_WAIT1();        // group 0 (A + k0) complete
    __syncthreads();

    // hoist A fragments into registers: [ks][f]
    unsigned ahr[4][2][4], alr[4][2][4];
#pragma unroll
    for (int ks = 0; ks < 4; ++ks) {
        const unsigned xbA = (unsigned)((ks * 32 + kbA) ^ p);
#pragma unroll
        for (int f = 0; f < 2; ++f) {
            LDSM4(ahr[ks][f][0], ahr[ks][f][1], ahr[ks][f][2], ahr[ks][f][3],
                  aA0 + f * 2048 + xbA);
            LDSM4(alr[ks][f][0], alr[ks][f][1], alr[ks][f][2], alr[ks][f][3],
                  aA0 + OFF_QL + f * 2048 + xbA);
        }
    }

    float rmin[4];
#pragma unroll
    for (int i = 0; i < 4; ++i) rmin[i] = 1e30f;

    float qnr0, qnr1;   // per-thread q norms for final fold (row mapping below)

    for (int i = 0; i < NT; ++i) {
        const unsigned bufb = sb + OFF_B + (i & 1) * BUFSZ;

        float acc[2][8][4];
#pragma unroll
        for (int t8 = 0; t8 < 8; ++t8) {
            float2 kn2 = *(const float2*)(smem + (i & 1) * BUFSZ + OFF_B + 32768
                                          + (wc + t8 * 8 + 2 * (l & 3)) * 4);
#pragma unroll
            for (int f = 0; f < 2; ++f) {
                acc[f][t8][0] = kn2.x; acc[f][t8][1] = kn2.y;
                acc[f][t8][2] = kn2.x; acc[f][t8][3] = kn2.y;
            }
        }

#pragma unroll
        for (int ks = 0; ks < 4; ++ks) {
            const unsigned xbB = (unsigned)((ks * 32 + kbB) ^ p);
            unsigned bh[8][2], bl[8][2];
#pragma unroll
            for (int g = 0; g < 4; ++g) {
                unsigned base = bufb + aB0 + g * 2048 + xbB;
                LDSM4(bh[2 * g][0], bh[2 * g][1], bh[2 * g + 1][0], bh[2 * g + 1][1], base);
                LDSM4(bl[2 * g][0], bl[2 * g][1], bl[2 * g + 1][0], bl[2 * g + 1][1], base + 16384);
            }
#pragma unroll
            for (int f = 0; f < 2; ++f)
#pragma unroll
                for (int t8 = 0; t8 < 8; ++t8) {
                    MMA16816(acc[f][t8], ahr[ks][f], bh[t8]);
                    MMA16816(acc[f][t8], ahr[ks][f], bl[t8]);
                    MMA16816(acc[f][t8], alr[ks][f], bh[t8]);
                }
        }

#pragma unroll
        for (int f = 0; f < 2; ++f)
#pragma unroll
            for (int t8 = 0; t8 < 8; ++t8) {
                rmin[f * 2]     = fminf(rmin[f * 2],     fminf(acc[f][t8][0], acc[f][t8][1]));
                rmin[f * 2 + 1] = fminf(rmin[f * 2 + 1], fminf(acc[f][t8][2], acc[f][t8][3]));
            }

        __syncthreads();   // all reads of buf(i&1) done
        if (i + 2 < NT) {
            const char* skh = gkh + (size_t)(i + 2) * 128 * KD * 2;
            const char* skl = gkl + (size_t)(i + 2) * 128 * KD * 2;
            unsigned nbuf = sb + OFF_B + (i & 1) * BUFSZ;
#pragma unroll
            for (int it = 0; it < 8; ++it) {
                int f = t + 256 * it;
                int split = f >> 10, c = f & 1023;
                int row = c >> 3, ch = c & 7;
                unsigned dst = nbuf + split * 16384 + row * 128 + ((ch * 16) ^ ((row & 7) << 4));
                CP16(dst, (split ? skl : skh) + c * 16);
            }
            if (t < 32) CP16(nbuf + 32768 + t * 16, gkn + (size_t)(i + 2) * 512 + t * 16);
            CP_COMMIT();
            CP_WAIT1();
            __syncthreads();
        } else if (i + 1 < NT) {
            CP_WAIT0();
            __syncthreads();
        }
    }

    float* s_red = (float*)(smem + OFF_RED);
    float* s_qn  = (float*)(smem + OFF_QN);
    __syncthreads();
#pragma unroll
    for (int f = 0; f < 2; ++f)
#pragma unroll
        for (int h = 0; h < 2; ++h) {
            int row = wr + f * 16 + (l >> 2) + h * 8;
            s_red[row * 8 + (wid >> 2) * 4 + (l & 3)] = rmin[f * 2 + h];
        }
    __syncthreads();
    if (t < 128) {
        float mv = s_red[t * 8];
#pragma unroll
        for (int j = 1; j < 8; ++j) mv = fminf(mv, s_red[t * 8 + j]);
        g_w[b * NN + n0 + t] = expf(-(mv + s_qn[t]));
    }
    (void)qnr0; (void)qnr1;
}

// =====================================================================
// Kernel 3: rank-1 outer product, streaming stores.
// =====================================================================
__global__ __launch_bounds__(256) void outer_kernel(float* __restrict__ out)
{
    const int b = blockIdx.y;
    const int n = blockIdx.x;
    const float wn = g_w[b * NN + n];
    const float4* wv = (const float4*)&g_w[b * NN];
    float4* o = (float4*)(out + ((size_t)b * NN + n) * MM);
#pragma unroll
    for (int it = 0; it < 2; ++it) {
        int j = threadIdx.x + 256 * it;
        float4 v = wv[j];
        __stcs(&o[j], make_float4(wn * v.x, wn * v.y, wn * v.z, wn * v.w));
    }
}

// =====================================================================
extern "C" void kernel_launch(void* const* d_in, const int* in_sizes, int n_in,
                              void* d_out, int out_size)
{
    const float* x  = (const float*)d_in[0];
    const float* y  = (const float*)d_in[1];
    const float* Wq = (const float*)d_in[2];
    const float* bq = (const float*)d_in[3];
    const float* Wk = (const float*)d_in[4];
    const float* bk = (const float*)d_in[5];
    float* out = (float*)d_out;

    cudaFuncSetAttribute(proj_kernel, cudaFuncAttributeMaxDynamicSharedMemorySize, PJ_SMEM);
    cudaFuncSetAttribute(dist_kernel, cudaFuncAttributeMaxDynamicSharedMemorySize, DIST_SMEM);

    wsplit_kernel<<<256, 256>>>(Wq, Wk);
    proj_kernel<<<dim3(NN * BB / 64, 2), 256, PJ_SMEM>>>(x, y, bq, bk);
    dist_kernel<<<dim3(NN / 128, BB), 256, DIST_SMEM>>>();
    outer_kernel<<<dim3(NN, BB), 256>>>(out);
}